// round 16
// baseline (speedup 1.0000x reference)
#include <cuda_runtime.h>
#include <cuda_bf16.h>
#include <cstdint>

#define B_      16
#define SQL     512
#define SKL     512
#define DMODEL  768
#define NH      12
#define HD_     64

// ---------------------------------------------------------------------------
// Static device scratch (allocation-free, graph-safe)
// ---------------------------------------------------------------------------
__device__ __nv_bfloat16 g_Hh[B_ * SQL * DMODEL];
__device__ __nv_bfloat16 g_Hl[B_ * SQL * DMODEL];
__device__ __nv_bfloat16 g_Ch[B_ * SKL * DMODEL];
__device__ __nv_bfloat16 g_Cl[B_ * SKL * DMODEL];
__device__ __nv_bfloat16 g_WTh[3][DMODEL * DMODEL];
__device__ __nv_bfloat16 g_WTl[3][DMODEL * DMODEL];
// projected Q/K/V bf16 hi/lo (Q pre-scaled by 0.125*log2e -> ex2 softmax)
__device__ __nv_bfloat16 g_Oh[3][B_ * SQL * DMODEL];
__device__ __nv_bfloat16 g_Ol[3][B_ * SQL * DMODEL];

// ---------------------------------------------------------------------------
__device__ __forceinline__ uint32_t smem_u32(const void* p) {
    uint32_t a;
    asm("{ .reg .u64 t; cvta.to.shared.u64 t, %1; cvt.u32.u64 %0, t; }" : "=r"(a) : "l"(p));
    return a;
}
#define CP_ASYNC16(dst, src) \
    asm volatile("cp.async.cg.shared.global [%0], [%1], 16;" :: "r"(dst), "l"(src))
#define CP_COMMIT() asm volatile("cp.async.commit_group;" ::: "memory")
#define CP_WAIT2()  asm volatile("cp.async.wait_group 2;" ::: "memory")
#define CP_WAIT1()  asm volatile("cp.async.wait_group 1;" ::: "memory")
#define CP_WAIT0()  asm volatile("cp.async.wait_group 0;" ::: "memory")

#define LDSM_X4(r, addr) \
    asm volatile("ldmatrix.sync.aligned.m8n8.x4.shared.b16 {%0,%1,%2,%3}, [%4];" \
        : "=r"((r)[0]), "=r"((r)[1]), "=r"((r)[2]), "=r"((r)[3]) : "r"(addr))
#define LDSM_X4_T(r, addr) \
    asm volatile("ldmatrix.sync.aligned.m8n8.x4.trans.shared.b16 {%0,%1,%2,%3}, [%4];" \
        : "=r"((r)[0]), "=r"((r)[1]), "=r"((r)[2]), "=r"((r)[3]) : "r"(addr))

__device__ __forceinline__ void mma16816(float* d, const uint32_t* a, const uint32_t* b)
{
    asm volatile(
        "mma.sync.aligned.m16n8k16.row.col.f32.bf16.bf16.f32 "
        "{%0,%1,%2,%3}, {%4,%5,%6,%7}, {%8,%9}, {%0,%1,%2,%3};"
        : "+f"(d[0]), "+f"(d[1]), "+f"(d[2]), "+f"(d[3])
        : "r"(a[0]), "r"(a[1]), "r"(a[2]), "r"(a[3]), "r"(b[0]), "r"(b[1]));
}

// Guaranteed single-instruction MUFU.EX2 (2^x), independent of fast-math flags.
__device__ __forceinline__ float ex2f(float x)
{
    float r;
    asm("ex2.approx.f32 %0, %1;" : "=f"(r) : "f"(x));
    return r;
}

__device__ __forceinline__ void split_bf16(float x, __nv_bfloat16& hi, __nv_bfloat16& lo)
{
    hi = __float2bfloat16_rn(x);
    lo = __float2bfloat16_rn(x - __bfloat162float(hi));
}
__device__ __forceinline__ uint32_t pack_bf2(__nv_bfloat16 a, __nv_bfloat16 b)
{
    __nv_bfloat162 t; t.x = a; t.y = b;
    return *(uint32_t*)&t;
}

// ---------------------------------------------------------------------------
// Fused pre-split: grid.y = 0 -> hidden, 1 -> context
// ---------------------------------------------------------------------------
__global__ void split_in(const float* __restrict__ H, const float* __restrict__ C,
                         __nv_bfloat16* __restrict__ Hh, __nv_bfloat16* __restrict__ Hl,
                         __nv_bfloat16* __restrict__ Chh, __nv_bfloat16* __restrict__ Cll)
{
    const float* X = (blockIdx.y == 0) ? H : C;
    __nv_bfloat16* Xh = (blockIdx.y == 0) ? Hh : Chh;
    __nv_bfloat16* Xl = (blockIdx.y == 0) ? Hl : Cll;
    int i = (blockIdx.x * blockDim.x + threadIdx.x) * 4;
    float4 v = *(const float4*)(X + i);
    __nv_bfloat162 h0, h1, l0, l1;
    split_bf16(v.x, h0.x, l0.x); split_bf16(v.y, h0.y, l0.y);
    split_bf16(v.z, h1.x, l1.x); split_bf16(v.w, h1.y, l1.y);
    *(__nv_bfloat162*)(Xh + i)     = h0;
    *(__nv_bfloat162*)(Xh + i + 2) = h1;
    *(__nv_bfloat162*)(Xl + i)     = l0;
    *(__nv_bfloat162*)(Xl + i + 2) = l1;
}

__global__ void transpose_w(const float* __restrict__ Wq, const float* __restrict__ Wk,
                            const float* __restrict__ Wv)
{
    __shared__ float tile[32][33];
    const float* W = (blockIdx.z == 0) ? Wq : ((blockIdx.z == 1) ? Wk : Wv);
    __nv_bfloat16* WTh = g_WTh[blockIdx.z];
    __nv_bfloat16* WTl = g_WTl[blockIdx.z];
    int x = blockIdx.x * 32 + threadIdx.x;
    int y = blockIdx.y * 32 + threadIdx.y;
#pragma unroll
    for (int j = 0; j < 32; j += 8)
        tile[threadIdx.y + j][threadIdx.x] = W[(y + j) * DMODEL + x];
    __syncthreads();
    x = blockIdx.y * 32 + threadIdx.x;
    y = blockIdx.x * 32 + threadIdx.y;
#pragma unroll
    for (int j = 0; j < 32; j += 8) {
        float v = tile[threadIdx.x][threadIdx.y + j];
        __nv_bfloat16 h, l;
        split_bf16(v, h, l);
        WTh[(y + j) * DMODEL + x] = h;
        WTl[(y + j) * DMODEL + x] = l;
    }
}

// ---------------------------------------------------------------------------
// FUSED projection GEMMs: 128x128 tile, 256 thr, 2 CTAs/SM, 4-stage ring,
// wait_group 2, refill AFTER compute (R12/R13 proven ordering).
// ---------------------------------------------------------------------------
#define APAD 24
#define ARR_B   (128 * APAD * 2)          // 6144 bytes per array
#define STAGE_B (4 * ARR_B)               // 24576 bytes per stage
#define NSTAGE  4
#define PROJ_SMEM (NSTAGE * STAGE_B)      // 98304 bytes

__global__ __launch_bounds__(256, 2)
void proj_mma(const __nv_bfloat16* __restrict__ Hh, const __nv_bfloat16* __restrict__ Hl,
              const __nv_bfloat16* __restrict__ Ch, const __nv_bfloat16* __restrict__ Cl,
              const float* __restrict__ bq, const float* __restrict__ bk,
              const float* __restrict__ bv)
{
    extern __shared__ __align__(16) __nv_bfloat16 PS[];
    const uint32_t sbase = smem_u32(PS);

    const int sel = blockIdx.z;
    const __nv_bfloat16* __restrict__ Ahg = (sel == 0) ? Hh : Ch;
    const __nv_bfloat16* __restrict__ Alg = (sel == 0) ? Hl : Cl;
    const float* __restrict__ bias = (sel == 0) ? bq : ((sel == 1) ? bk : bv);
    __nv_bfloat16* __restrict__ Oh = g_Oh[sel];
    __nv_bfloat16* __restrict__ Ol = g_Ol[sel];
    const __nv_bfloat16* __restrict__ Bhg = g_WTh[sel];
    const __nv_bfloat16* __restrict__ Blg = g_WTl[sel];
    // Q carries 1/sqrt(64) * log2(e) so attention softmax can use ex2
    const float scale = (sel == 0) ? 0.125f * 1.4426950408889634f : 1.0f;

    const int tid = threadIdx.x;
    const int lane = tid & 31;
    const int wid = tid >> 5;
    const int warp_m = wid >> 2;
    const int warp_n = wid & 3;
    const int bm = blockIdx.y * 128;
    const int bn = blockIdx.x * 128;

    const int lr = tid >> 1;
    const int lh = (tid & 1) * 8;
    const size_t arow = (size_t)(bm + lr) * DMODEL + lh;
    const size_t brow = (size_t)(bn + lr) * DMODEL + lh;
    const uint32_t ldst = (uint32_t)(lr * APAD + lh) * 2;

    const uint32_t aoffA = ((warp_m * 64 + (lane & 15)) * APAD + (lane >> 4) * 8) * 2;
    const uint32_t aoffB = ((warp_n * 32 + ((lane >> 4) << 3) + (lane & 7)) * APAD
                            + ((lane >> 3) & 1) * 8) * 2;

    const int fr = lane >> 2;
    const int fk = (lane & 3) * 2;

    float acc[4][4][4];
#pragma unroll
    for (int i = 0; i < 4; i++)
#pragma unroll
        for (int j = 0; j < 4; j++)
#pragma unroll
            for (int r = 0; r < 4; r++) acc[i][j][r] = 0.f;

    const int NCH = DMODEL / 16;   // 48

#pragma unroll
    for (int c = 0; c < 3; c++) {
        uint32_t so = c * STAGE_B;
        int k0 = c * 16;
        CP_ASYNC16(sbase + so + 0 * ARR_B + ldst, Ahg + arow + k0);
        CP_ASYNC16(sbase + so + 1 * ARR_B + ldst, Alg + arow + k0);
        CP_ASYNC16(sbase + so + 2 * ARR_B + ldst, Bhg + brow + k0);
        CP_ASYNC16(sbase + so + 3 * ARR_B + ldst, Blg + brow + k0);
        CP_COMMIT();
    }

    for (int c = 0; c < NCH; c++) {
        const uint32_t so = (uint32_t)(c & (NSTAGE - 1)) * STAGE_B;
        CP_WAIT2();
        __syncthreads();

        uint32_t fah[4][4], fal[4][4], fbh4[2][4], fbl4[2][4];
#pragma unroll
        for (int mt = 0; mt < 4; mt++) {
            LDSM_X4(fah[mt], sbase + so + 0 * ARR_B + aoffA + mt * 768);
            LDSM_X4(fal[mt], sbase + so + 1 * ARR_B + aoffA + mt * 768);
        }
#pragma unroll
        for (int pr = 0; pr < 2; pr++) {
            LDSM_X4(fbh4[pr], sbase + so + 2 * ARR_B + aoffB + pr * 768);
            LDSM_X4(fbl4[pr], sbase + so + 3 * ARR_B + aoffB + pr * 768);
        }

#pragma unroll
        for (int mt = 0; mt < 4; mt++)
#pragma unroll
            for (int nt = 0; nt < 4; nt++) {
                const uint32_t* bh = &fbh4[nt >> 1][(nt & 1) * 2];
                const uint32_t* bl = &fbl4[nt >> 1][(nt & 1) * 2];
                mma16816(acc[mt][nt], fah[mt], bh);
                mma16816(acc[mt][nt], fah[mt], bl);
                mma16816(acc[mt][nt], fal[mt], bh);
            }

        // refill chunk c+3 -> stage (c-1)&3 (readers done last iteration)
        if (c + 3 < NCH) {
            uint32_t so2 = (uint32_t)((c + 3) & (NSTAGE - 1)) * STAGE_B;
            int k0 = (c + 3) * 16;
            CP_ASYNC16(sbase + so2 + 0 * ARR_B + ldst, Ahg + arow + k0);
            CP_ASYNC16(sbase + so2 + 1 * ARR_B + ldst, Alg + arow + k0);
            CP_ASYNC16(sbase + so2 + 2 * ARR_B + ldst, Bhg + brow + k0);
            CP_ASYNC16(sbase + so2 + 3 * ARR_B + ldst, Blg + brow + k0);
        }
        CP_COMMIT();
    }

#pragma unroll
    for (int mt = 0; mt < 4; mt++) {
#pragma unroll
        for (int nt = 0; nt < 4; nt++) {
            int rg = bm + warp_m * 64 + mt * 16 + fr;
            int cg = bn + warp_n * 32 + nt * 8 + fk;
            float b0 = __ldg(bias + cg), b1 = __ldg(bias + cg + 1);
            float v00 = (acc[mt][nt][0] + b0) * scale;
            float v01 = (acc[mt][nt][1] + b1) * scale;
            float v10 = (acc[mt][nt][2] + b0) * scale;
            float v11 = (acc[mt][nt][3] + b1) * scale;
            __nv_bfloat16 h, l;
            __nv_bfloat162 hh, ll;
            split_bf16(v00, h, l); hh.x = h; ll.x = l;
            split_bf16(v01, h, l); hh.y = h; ll.y = l;
            *(__nv_bfloat162*)&Oh[(size_t)rg * DMODEL + cg] = hh;
            *(__nv_bfloat162*)&Ol[(size_t)rg * DMODEL + cg] = ll;
            split_bf16(v10, h, l); hh.x = h; ll.x = l;
            split_bf16(v11, h, l); hh.y = h; ll.y = l;
            *(__nv_bfloat162*)&Oh[(size_t)(rg + 8) * DMODEL + cg] = hh;
            *(__nv_bfloat162*)&Ol[(size_t)(rg + 8) * DMODEL + cg] = ll;
        }
    }
}

// ---------------------------------------------------------------------------
// HMMA flash attention, phase-pipelined loads, ex2.approx softmax.
// ---------------------------------------------------------------------------
#define VP 88

__global__ __launch_bounds__(128)
void attn_mma(float* __restrict__ Out)
{
    __shared__ __nv_bfloat16 Kh[64][VP];
    __shared__ __nv_bfloat16 Kl[64][VP];
    __shared__ __nv_bfloat16 Vh[64][VP];
    __shared__ __nv_bfloat16 Vl[64][VP];

    const int tid = threadIdx.x;
    const int lane = tid & 31;
    const int wid = tid >> 5;
    const int b  = blockIdx.z;
    const int h  = blockIdx.y;
    const int q0 = blockIdx.x * 64;

    const int fr = lane >> 2;
    const int fk = (lane & 3) * 2;

    const __nv_bfloat16* __restrict__ Qh = g_Oh[0];
    const __nv_bfloat16* __restrict__ Ql = g_Ol[0];
    const __nv_bfloat16* __restrict__ Kgh = g_Oh[1];
    const __nv_bfloat16* __restrict__ Kgl = g_Ol[1];
    const __nv_bfloat16* __restrict__ Vgh = g_Oh[2];
    const __nv_bfloat16* __restrict__ Vgl = g_Ol[2];

    const int lr = tid >> 1;
    const int lh = (tid & 1) * 32;
    const uint32_t aKh = smem_u32(&Kh[lr][lh]);
    const uint32_t aKl = smem_u32(&Kl[lr][lh]);
    const uint32_t aVh = smem_u32(&Vh[lr][lh]);
    const uint32_t aVl = smem_u32(&Vl[lr][lh]);

    const uint32_t bKh = smem_u32(Kh);
    const uint32_t bKl = smem_u32(Kl);
    const uint32_t bVh = smem_u32(Vh);
    const uint32_t bVl = smem_u32(Vl);

    const uint32_t qoff = ((wid * 16 + (lane & 15)) * VP + (lane >> 4) * 8) * 2;
    const uint32_t koff = (((lane >> 4) * 8 + (lane & 7)) * VP + ((lane >> 3) & 1) * 8) * 2;
    const uint32_t voff = ((((lane >> 3) & 1) * 8 + (lane & 7)) * VP + (lane >> 4) * 8) * 2;

    const size_t kvbase = ((size_t)(b * SKL + lr)) * DMODEL + h * HD_ + lh;

    // ---- stage Q through Kh/Kl, extract fragments ----
    {
        const __nv_bfloat16* qh = Qh + ((size_t)(b * SQL + q0 + lr)) * DMODEL + h * HD_ + lh;
        const __nv_bfloat16* ql = Ql + ((size_t)(b * SQL + q0 + lr)) * DMODEL + h * HD_ + lh;
#pragma unroll
        for (int j = 0; j < 4; j++) {
            CP_ASYNC16(aKh + j * 16, qh + j * 8);
            CP_ASYNC16(aKl + j * 16, ql + j * 8);
        }
        CP_COMMIT();
        CP_WAIT0();
        __syncthreads();
    }
    uint32_t qfh[4][4], qfl[4][4];
#pragma unroll
    for (int kc = 0; kc < 4; kc++) {
        LDSM_X4(qfh[kc], bKh + qoff + kc * 32);
        LDSM_X4(qfl[kc], bKl + qoff + kc * 32);
    }
    __syncthreads();   // done reading Kh/Kl (Q staging) before K(0) overwrites

    // ---- prologue: K(0) group, then V(0) group ----
    {
        const __nv_bfloat16* kh = Kgh + kvbase;
        const __nv_bfloat16* kl = Kgl + kvbase;
#pragma unroll
        for (int j = 0; j < 4; j++) {
            CP_ASYNC16(aKh + j * 16, kh + j * 8);
            CP_ASYNC16(aKl + j * 16, kl + j * 8);
        }
        CP_COMMIT();
        const __nv_bfloat16* vh = Vgh + kvbase;
        const __nv_bfloat16* vl = Vgl + kvbase;
#pragma unroll
        for (int j = 0; j < 4; j++) {
            CP_ASYNC16(aVh + j * 16, vh + j * 8);
            CP_ASYNC16(aVl + j * 16, vl + j * 8);
        }
        CP_COMMIT();
    }

    float m0 = -1e30f, m1 = -1e30f, l0 = 0.f, l1 = 0.f;
    float accO[8][4];
#pragma unroll
    for (int dt = 0; dt < 8; dt++)
#pragma unroll
        for (int r = 0; r < 4; r++) accO[dt][r] = 0.f;

    for (int t = 0; t < 8; t++) {
        // ---- K(t) ready (V(t) may still be in flight) ----
        CP_WAIT1();
        __syncthreads();

        // ---- S' = (Q*log2e/8) K^T  (log2 domain) ----
        float accS[8][4];
#pragma unroll
        for (int pr = 0; pr < 4; pr++) {
            uint32_t kh4[4][4], kl4[4][4];
#pragma unroll
            for (int kc = 0; kc < 4; kc++) {
                LDSM_X4(kh4[kc], bKh + koff + pr * (16 * VP * 2) + kc * 32);
                LDSM_X4(kl4[kc], bKl + koff + pr * (16 * VP * 2) + kc * 32);
            }
            int n0 = 2 * pr, n1 = 2 * pr + 1;
            accS[n0][0] = accS[n0][1] = accS[n0][2] = accS[n0][3] = 0.f;
            accS[n1][0] = accS[n1][1] = accS[n1][2] = accS[n1][3] = 0.f;
#pragma unroll
            for (int kc = 0; kc < 4; kc++) {
                mma16816(accS[n0], qfh[kc], &kh4[kc][0]);
                mma16816(accS[n0], qfh[kc], &kl4[kc][0]);
                mma16816(accS[n0], qfl[kc], &kh4[kc][0]);
                mma16816(accS[n1], qfh[kc], &kh4[kc][2]);
                mma16816(accS[n1], qfh[kc], &kl4[kc][2]);
                mma16816(accS[n1], qfl[kc], &kh4[kc][2]);
            }
        }

        // ---- done reading K: prefetch K(t+1) under softmax+PV ----
        __syncthreads();
        if (t + 1 < 8) {
            const size_t off = kvbase + (size_t)(t + 1) * 64 * DMODEL;
            const __nv_bfloat16* kh = Kgh + off;
            const __nv_bfloat16* kl = Kgl + off;
#pragma unroll
            for (int j = 0; j < 4; j++) {
                CP_ASYNC16(aKh + j * 16, kh + j * 8);
                CP_ASYNC16(aKl + j * 16, kl + j * 8);
            }
        }
        CP_COMMIT();

        // ---- online softmax, ex2 domain (single MUFU per value) ----
        float mt0 = -1e30f, mt1 = -1e30f;
#pragma unroll
        for (int nt = 0; nt < 8; nt++) {
            mt0 = fmaxf(mt0, fmaxf(accS[nt][0], accS[nt][1]));
            mt1 = fmaxf(mt1, fmaxf(accS[nt][2], accS[nt][3]));
        }
        mt0 = fmaxf(mt0, __shfl_xor_sync(0xffffffffu, mt0, 1));
        mt0 = fmaxf(mt0, __shfl_xor_sync(0xffffffffu, mt0, 2));
        mt1 = fmaxf(mt1, __shfl_xor_sync(0xffffffffu, mt1, 1));
        mt1 = fmaxf(mt1, __shfl_xor_sync(0xffffffffu, mt1, 2));

        float mn0 = fmaxf(m0, mt0), mn1 = fmaxf(m1, mt1);
        float c0 = ex2f(m0 - mn0), c1 = ex2f(m1 - mn1);
        m0 = mn0; m1 = mn1;

        float s0 = 0.f, s1 = 0.f;
#pragma unroll
        for (int nt = 0; nt < 8; nt++) {
            accS[nt][0] = ex2f(accS[nt][0] - mn0);
            accS[nt][1] = ex2f(accS[nt][1] - mn0);
            accS[nt][2] = ex2f(accS[nt][2] - mn1);
            accS[nt][3] = ex2f(accS[nt][3] - mn1);
            s0 += accS[nt][0] + accS[nt][1];
            s1 += accS[nt][2] + accS[nt][3];
        }
        s0 += __shfl_xor_sync(0xffffffffu, s0, 1);
        s0 += __shfl_xor_sync(0xffffffffu, s0, 2);
        s1 += __shfl_xor_sync(0xffffffffu, s1, 1);
        s1 += __shfl_xor_sync(0xffffffffu, s1, 2);
        l0 = l0 * c0 + s0;
        l1 = l1 * c1 + s1;
#pragma unroll
        for (int dt = 0; dt < 8; dt++) {
            accO[dt][0] *= c0; accO[dt][1] *= c0;
            accO[dt][2] *= c1; accO[dt][3] *= c1;
        }

        // ---- P fragments in registers (hi/lo) ----
        uint32_t pfh[4][4], pfl[4][4];
#pragma unroll
        for (int kc = 0; kc < 4; kc++) {
            __nv_bfloat16 h00, l00, h01, l01;
            split_bf16(accS[2 * kc][0], h00, l00);
            split_bf16(accS[2 * kc][1], h01, l01);
            pfh[kc][0] = pack_bf2(h00, h01);
            pfl[kc][0] = pack_bf2(l00, l01);
            split_bf16(accS[2 * kc][2], h00, l00);
            split_bf16(accS[2 * kc][3], h01, l01);
            pfh[kc][1] = pack_bf2(h00, h01);
            pfl[kc][1] = pack_bf2(l00, l01);
            split_bf16(accS[2 * kc + 1][0], h00, l00);
            split_bf16(accS[2 * kc + 1][1], h01, l01);
            pfh[kc][2] = pack_bf2(h00, h01);
            pfl[kc][2] = pack_bf2(l00, l01);
            split_bf16(accS[2 * kc + 1][2], h00, l00);
            split_bf16(accS[2 * kc + 1][3], h01, l01);
            pfh[kc][3] = pack_bf2(h00, h01);
            pfl[kc][3] = pack_bf2(l00, l01);
        }

        // ---- V(t) ready (K(t+1) may still be in flight) ----
        CP_WAIT1();
        __syncthreads();

        // ---- O += P V ----
#pragma unroll
        for (int pr = 0; pr < 4; pr++) {
            uint32_t vh4[4][4], vl4[4][4];
#pragma unroll
            for (int kc = 0; kc < 4; kc++) {
                LDSM_X4_T(vh4[kc], bVh + voff + kc * (16 * VP * 2) + pr * 32);
                LDSM_X4_T(vl4[kc], bVl + voff + kc * (16 * VP * 2) + pr * 32);
            }
            int d0 = 2 * pr, d1 = 2 * pr + 1;
#pragma unroll
            for (int kc = 0; kc < 4; kc++) {
                mma16816(accO[d0], pfh[kc], &vh4[kc][0]);
                mma16816(accO[d0], pfh[kc], &vl4[kc][0]);
                mma16816(accO[d0], pfl[kc], &vh4[kc][0]);
                mma16816(accO[d1], pfh[kc], &vh4[kc][2]);
                mma16816(accO[d1], pfh[kc], &vl4[kc][2]);
                mma16816(accO[d1], pfl[kc], &vh4[kc][2]);
            }
        }

        // ---- done reading V: prefetch V(t+1) under next tile's S ----
        __syncthreads();
        if (t + 1 < 8) {
            const size_t off = kvbase + (size_t)(t + 1) * 64 * DMODEL;
            const __nv_bfloat16* vh = Vgh + off;
            const __nv_bfloat16* vl = Vgl + off;
#pragma unroll
            for (int j = 0; j < 4; j++) {
                CP_ASYNC16(aVh + j * 16, vh + j * 8);
                CP_ASYNC16(aVl + j * 16, vl + j * 8);
            }
        }
        CP_COMMIT();
    }

    float inv0 = 1.f / l0, inv1 = 1.f / l1;
    int row0 = b * SQL + q0 + wid * 16 + fr;
#pragma unroll
    for (int dt = 0; dt < 8; dt++) {
        int col = h * HD_ + dt * 8 + fk;
        float2 o0 = { accO[dt][0] * inv0, accO[dt][1] * inv0 };
        float2 o1 = { accO[dt][2] * inv1, accO[dt][3] * inv1 };
        *(float2*)&Out[(size_t)row0 * DMODEL + col] = o0;
        *(float2*)&Out[(size_t)(row0 + 8) * DMODEL + col] = o1;
    }
}

// ---------------------------------------------------------------------------
extern "C" void kernel_launch(void* const* d_in, const int* in_sizes, int n_in,
                              void* d_out, int out_size)
{
    const float* hidden  = (const float*)d_in[0];
    const float* context = (const float*)d_in[1];
    const float* Wq = (const float*)d_in[2];
    const float* bq = (const float*)d_in[3];
    const float* Wk = (const float*)d_in[4];
    const float* bk = (const float*)d_in[5];
    const float* Wv = (const float*)d_in[6];
    const float* bv = (const float*)d_in[7];
    float* out = (float*)d_out;

    static __nv_bfloat16 *hh = nullptr, *hl = nullptr, *ch = nullptr, *cl = nullptr;
    if (!hh) {
        cudaGetSymbolAddress((void**)&hh, g_Hh);
        cudaGetSymbolAddress((void**)&hl, g_Hl);
        cudaGetSymbolAddress((void**)&ch, g_Ch);
        cudaGetSymbolAddress((void**)&cl, g_Cl);
        cudaFuncSetAttribute(proj_mma, cudaFuncAttributeMaxDynamicSharedMemorySize, PROJ_SMEM);
    }

    const int NEL = B_ * SQL * DMODEL;
    dim3 sgrid(NEL / 4 / 256, 2);
    split_in<<<sgrid, 256>>>(hidden, context, hh, hl, ch, cl);

    dim3 tgrid(DMODEL / 32, DMODEL / 32, 3);
    transpose_w<<<tgrid, dim3(32, 8)>>>(Wq, Wk, Wv);

    dim3 pgrid(DMODEL / 128, (B_ * SQL) / 128, 3);   // (6, 64, 3) = 1152 CTAs
    proj_mma<<<pgrid, 256, PROJ_SMEM>>>(hh, hl, ch, cl, bq, bk, bv);

    dim3 agrid(SQL / 64, NH, B_);                    // (8, 12, 16)
    attn_mma<<<agrid, 128>>>(out);
}

// round 17
// speedup vs baseline: 1.0092x; 1.0092x over previous
#include <cuda_runtime.h>
#include <cuda_bf16.h>
#include <cstdint>

#define B_      16
#define SQL     512
#define SKL     512
#define DMODEL  768
#define NH      12
#define HD_     64

// ---------------------------------------------------------------------------
// Static device scratch (allocation-free, graph-safe)
// ---------------------------------------------------------------------------
__device__ __nv_bfloat16 g_Hh[B_ * SQL * DMODEL];
__device__ __nv_bfloat16 g_Hl[B_ * SQL * DMODEL];
__device__ __nv_bfloat16 g_Ch[B_ * SKL * DMODEL];
__device__ __nv_bfloat16 g_Cl[B_ * SKL * DMODEL];
__device__ __nv_bfloat16 g_WTh[3][DMODEL * DMODEL];
__device__ __nv_bfloat16 g_WTl[3][DMODEL * DMODEL];
// projected Q/K/V bf16 hi/lo (Q pre-scaled by 0.125*log2e -> ex2 softmax)
__device__ __nv_bfloat16 g_Oh[3][B_ * SQL * DMODEL];
__device__ __nv_bfloat16 g_Ol[3][B_ * SQL * DMODEL];

// ---------------------------------------------------------------------------
__device__ __forceinline__ uint32_t smem_u32(const void* p) {
    uint32_t a;
    asm("{ .reg .u64 t; cvta.to.shared.u64 t, %1; cvt.u32.u64 %0, t; }" : "=r"(a) : "l"(p));
    return a;
}
#define CP_ASYNC16(dst, src) \
    asm volatile("cp.async.cg.shared.global [%0], [%1], 16;" :: "r"(dst), "l"(src))
#define CP_COMMIT() asm volatile("cp.async.commit_group;" ::: "memory")
#define CP_WAIT2()  asm volatile("cp.async.wait_group 2;" ::: "memory")
#define CP_WAIT1()  asm volatile("cp.async.wait_group 1;" ::: "memory")
#define CP_WAIT0()  asm volatile("cp.async.wait_group 0;" ::: "memory")

#define LDSM_X4(r, addr) \
    asm volatile("ldmatrix.sync.aligned.m8n8.x4.shared.b16 {%0,%1,%2,%3}, [%4];" \
        : "=r"((r)[0]), "=r"((r)[1]), "=r"((r)[2]), "=r"((r)[3]) : "r"(addr))
#define LDSM_X4_T(r, addr) \
    asm volatile("ldmatrix.sync.aligned.m8n8.x4.trans.shared.b16 {%0,%1,%2,%3}, [%4];" \
        : "=r"((r)[0]), "=r"((r)[1]), "=r"((r)[2]), "=r"((r)[3]) : "r"(addr))

__device__ __forceinline__ void mma16816(float* d, const uint32_t* a, const uint32_t* b)
{
    asm volatile(
        "mma.sync.aligned.m16n8k16.row.col.f32.bf16.bf16.f32 "
        "{%0,%1,%2,%3}, {%4,%5,%6,%7}, {%8,%9}, {%0,%1,%2,%3};"
        : "+f"(d[0]), "+f"(d[1]), "+f"(d[2]), "+f"(d[3])
        : "r"(a[0]), "r"(a[1]), "r"(a[2]), "r"(a[3]), "r"(b[0]), "r"(b[1]));
}

// Guaranteed single-instruction MUFU.EX2 (2^x), independent of fast-math flags.
__device__ __forceinline__ float ex2f(float x)
{
    float r;
    asm("ex2.approx.f32 %0, %1;" : "=f"(r) : "f"(x));
    return r;
}

__device__ __forceinline__ void split_bf16(float x, __nv_bfloat16& hi, __nv_bfloat16& lo)
{
    hi = __float2bfloat16_rn(x);
    lo = __float2bfloat16_rn(x - __bfloat162float(hi));
}
__device__ __forceinline__ uint32_t pack_bf2(__nv_bfloat16 a, __nv_bfloat16 b)
{
    __nv_bfloat162 t; t.x = a; t.y = b;
    return *(uint32_t*)&t;
}

// ---------------------------------------------------------------------------
// Fused pre-split: grid.y = 0 -> hidden, 1 -> context
// ---------------------------------------------------------------------------
__global__ void split_in(const float* __restrict__ H, const float* __restrict__ C,
                         __nv_bfloat16* __restrict__ Hh, __nv_bfloat16* __restrict__ Hl,
                         __nv_bfloat16* __restrict__ Chh, __nv_bfloat16* __restrict__ Cll)
{
    const float* X = (blockIdx.y == 0) ? H : C;
    __nv_bfloat16* Xh = (blockIdx.y == 0) ? Hh : Chh;
    __nv_bfloat16* Xl = (blockIdx.y == 0) ? Hl : Cll;
    int i = (blockIdx.x * blockDim.x + threadIdx.x) * 4;
    float4 v = *(const float4*)(X + i);
    __nv_bfloat162 h0, h1, l0, l1;
    split_bf16(v.x, h0.x, l0.x); split_bf16(v.y, h0.y, l0.y);
    split_bf16(v.z, h1.x, l1.x); split_bf16(v.w, h1.y, l1.y);
    *(__nv_bfloat162*)(Xh + i)     = h0;
    *(__nv_bfloat162*)(Xh + i + 2) = h1;
    *(__nv_bfloat162*)(Xl + i)     = l0;
    *(__nv_bfloat162*)(Xl + i + 2) = l1;
}

__global__ void transpose_w(const float* __restrict__ Wq, const float* __restrict__ Wk,
                            const float* __restrict__ Wv)
{
    __shared__ float tile[32][33];
    const float* W = (blockIdx.z == 0) ? Wq : ((blockIdx.z == 1) ? Wk : Wv);
    __nv_bfloat16* WTh = g_WTh[blockIdx.z];
    __nv_bfloat16* WTl = g_WTl[blockIdx.z];
    int x = blockIdx.x * 32 + threadIdx.x;
    int y = blockIdx.y * 32 + threadIdx.y;
#pragma unroll
    for (int j = 0; j < 32; j += 8)
        tile[threadIdx.y + j][threadIdx.x] = W[(y + j) * DMODEL + x];
    __syncthreads();
    x = blockIdx.y * 32 + threadIdx.x;
    y = blockIdx.x * 32 + threadIdx.y;
#pragma unroll
    for (int j = 0; j < 32; j += 8) {
        float v = tile[threadIdx.x][threadIdx.y + j];
        __nv_bfloat16 h, l;
        split_bf16(v, h, l);
        WTh[(y + j) * DMODEL + x] = h;
        WTl[(y + j) * DMODEL + x] = l;
    }
}

// ---------------------------------------------------------------------------
// FUSED projection GEMMs: 128x128 tile, 256 thr, 2 CTAs/SM, 4-stage ring,
// wait_group 2, refill AFTER compute (R12/R13/R16 proven ordering).
// ---------------------------------------------------------------------------
#define APAD 24
#define ARR_B   (128 * APAD * 2)          // 6144 bytes per array
#define STAGE_B (4 * ARR_B)               // 24576 bytes per stage
#define NSTAGE  4
#define PROJ_SMEM (NSTAGE * STAGE_B)      // 98304 bytes

__global__ __launch_bounds__(256, 2)
void proj_mma(const __nv_bfloat16* __restrict__ Hh, const __nv_bfloat16* __restrict__ Hl,
              const __nv_bfloat16* __restrict__ Ch, const __nv_bfloat16* __restrict__ Cl,
              const float* __restrict__ bq, const float* __restrict__ bk,
              const float* __restrict__ bv)
{
    extern __shared__ __align__(16) __nv_bfloat16 PS[];
    const uint32_t sbase = smem_u32(PS);

    const int sel = blockIdx.z;
    const __nv_bfloat16* __restrict__ Ahg = (sel == 0) ? Hh : Ch;
    const __nv_bfloat16* __restrict__ Alg = (sel == 0) ? Hl : Cl;
    const float* __restrict__ bias = (sel == 0) ? bq : ((sel == 1) ? bk : bv);
    __nv_bfloat16* __restrict__ Oh = g_Oh[sel];
    __nv_bfloat16* __restrict__ Ol = g_Ol[sel];
    const __nv_bfloat16* __restrict__ Bhg = g_WTh[sel];
    const __nv_bfloat16* __restrict__ Blg = g_WTl[sel];
    // Q carries 1/sqrt(64) * log2(e) so attention softmax can use ex2
    const float scale = (sel == 0) ? 0.125f * 1.4426950408889634f : 1.0f;

    const int tid = threadIdx.x;
    const int lane = tid & 31;
    const int wid = tid >> 5;
    const int warp_m = wid >> 2;
    const int warp_n = wid & 3;
    const int bm = blockIdx.y * 128;
    const int bn = blockIdx.x * 128;

    const int lr = tid >> 1;
    const int lh = (tid & 1) * 8;
    const size_t arow = (size_t)(bm + lr) * DMODEL + lh;
    const size_t brow = (size_t)(bn + lr) * DMODEL + lh;
    const uint32_t ldst = (uint32_t)(lr * APAD + lh) * 2;

    const uint32_t aoffA = ((warp_m * 64 + (lane & 15)) * APAD + (lane >> 4) * 8) * 2;
    const uint32_t aoffB = ((warp_n * 32 + ((lane >> 4) << 3) + (lane & 7)) * APAD
                            + ((lane >> 3) & 1) * 8) * 2;

    const int fr = lane >> 2;
    const int fk = (lane & 3) * 2;

    float acc[4][4][4];
#pragma unroll
    for (int i = 0; i < 4; i++)
#pragma unroll
        for (int j = 0; j < 4; j++)
#pragma unroll
            for (int r = 0; r < 4; r++) acc[i][j][r] = 0.f;

    const int NCH = DMODEL / 16;   // 48

#pragma unroll
    for (int c = 0; c < 3; c++) {
        uint32_t so = c * STAGE_B;
        int k0 = c * 16;
        CP_ASYNC16(sbase + so + 0 * ARR_B + ldst, Ahg + arow + k0);
        CP_ASYNC16(sbase + so + 1 * ARR_B + ldst, Alg + arow + k0);
        CP_ASYNC16(sbase + so + 2 * ARR_B + ldst, Bhg + brow + k0);
        CP_ASYNC16(sbase + so + 3 * ARR_B + ldst, Blg + brow + k0);
        CP_COMMIT();
    }

    for (int c = 0; c < NCH; c++) {
        const uint32_t so = (uint32_t)(c & (NSTAGE - 1)) * STAGE_B;
        CP_WAIT2();
        __syncthreads();

        uint32_t fah[4][4], fal[4][4], fbh4[2][4], fbl4[2][4];
#pragma unroll
        for (int mt = 0; mt < 4; mt++) {
            LDSM_X4(fah[mt], sbase + so + 0 * ARR_B + aoffA + mt * 768);
            LDSM_X4(fal[mt], sbase + so + 1 * ARR_B + aoffA + mt * 768);
        }
#pragma unroll
        for (int pr = 0; pr < 2; pr++) {
            LDSM_X4(fbh4[pr], sbase + so + 2 * ARR_B + aoffB + pr * 768);
            LDSM_X4(fbl4[pr], sbase + so + 3 * ARR_B + aoffB + pr * 768);
        }

#pragma unroll
        for (int mt = 0; mt < 4; mt++)
#pragma unroll
            for (int nt = 0; nt < 4; nt++) {
                const uint32_t* bh = &fbh4[nt >> 1][(nt & 1) * 2];
                const uint32_t* bl = &fbl4[nt >> 1][(nt & 1) * 2];
                mma16816(acc[mt][nt], fah[mt], bh);
                mma16816(acc[mt][nt], fah[mt], bl);
                mma16816(acc[mt][nt], fal[mt], bh);
            }

        // refill chunk c+3 -> stage (c-1)&3 (readers done last iteration)
        if (c + 3 < NCH) {
            uint32_t so2 = (uint32_t)((c + 3) & (NSTAGE - 1)) * STAGE_B;
            int k0 = (c + 3) * 16;
            CP_ASYNC16(sbase + so2 + 0 * ARR_B + ldst, Ahg + arow + k0);
            CP_ASYNC16(sbase + so2 + 1 * ARR_B + ldst, Alg + arow + k0);
            CP_ASYNC16(sbase + so2 + 2 * ARR_B + ldst, Bhg + brow + k0);
            CP_ASYNC16(sbase + so2 + 3 * ARR_B + ldst, Blg + brow + k0);
        }
        CP_COMMIT();
    }

#pragma unroll
    for (int mt = 0; mt < 4; mt++) {
#pragma unroll
        for (int nt = 0; nt < 4; nt++) {
            int rg = bm + warp_m * 64 + mt * 16 + fr;
            int cg = bn + warp_n * 32 + nt * 8 + fk;
            float b0 = __ldg(bias + cg), b1 = __ldg(bias + cg + 1);
            float v00 = (acc[mt][nt][0] + b0) * scale;
            float v01 = (acc[mt][nt][1] + b1) * scale;
            float v10 = (acc[mt][nt][2] + b0) * scale;
            float v11 = (acc[mt][nt][3] + b1) * scale;
            __nv_bfloat16 h, l;
            __nv_bfloat162 hh, ll;
            split_bf16(v00, h, l); hh.x = h; ll.x = l;
            split_bf16(v01, h, l); hh.y = h; ll.y = l;
            *(__nv_bfloat162*)&Oh[(size_t)rg * DMODEL + cg] = hh;
            *(__nv_bfloat162*)&Ol[(size_t)rg * DMODEL + cg] = ll;
            split_bf16(v10, h, l); hh.x = h; ll.x = l;
            split_bf16(v11, h, l); hh.y = h; ll.y = l;
            *(__nv_bfloat162*)&Oh[(size_t)(rg + 8) * DMODEL + cg] = hh;
            *(__nv_bfloat162*)&Ol[(size_t)(rg + 8) * DMODEL + cg] = ll;
        }
    }
}

// ---------------------------------------------------------------------------
// HMMA flash attention, phase-pipelined loads, ex2.approx softmax.
// __launch_bounds__(128, 4): force <=128 regs -> 4 CTAs/SM (16 warps).
// ---------------------------------------------------------------------------
#define VP 88

__global__ __launch_bounds__(128, 4)
void attn_mma(float* __restrict__ Out)
{
    __shared__ __nv_bfloat16 Kh[64][VP];
    __shared__ __nv_bfloat16 Kl[64][VP];
    __shared__ __nv_bfloat16 Vh[64][VP];
    __shared__ __nv_bfloat16 Vl[64][VP];

    const int tid = threadIdx.x;
    const int lane = tid & 31;
    const int wid = tid >> 5;
    const int b  = blockIdx.z;
    const int h  = blockIdx.y;
    const int q0 = blockIdx.x * 64;

    const int fr = lane >> 2;
    const int fk = (lane & 3) * 2;

    const __nv_bfloat16* __restrict__ Qh = g_Oh[0];
    const __nv_bfloat16* __restrict__ Ql = g_Ol[0];
    const __nv_bfloat16* __restrict__ Kgh = g_Oh[1];
    const __nv_bfloat16* __restrict__ Kgl = g_Ol[1];
    const __nv_bfloat16* __restrict__ Vgh = g_Oh[2];
    const __nv_bfloat16* __restrict__ Vgl = g_Ol[2];

    const int lr = tid >> 1;
    const int lh = (tid & 1) * 32;
    const uint32_t aKh = smem_u32(&Kh[lr][lh]);
    const uint32_t aKl = smem_u32(&Kl[lr][lh]);
    const uint32_t aVh = smem_u32(&Vh[lr][lh]);
    const uint32_t aVl = smem_u32(&Vl[lr][lh]);

    const uint32_t bKh = smem_u32(Kh);
    const uint32_t bKl = smem_u32(Kl);
    const uint32_t bVh = smem_u32(Vh);
    const uint32_t bVl = smem_u32(Vl);

    const uint32_t qoff = ((wid * 16 + (lane & 15)) * VP + (lane >> 4) * 8) * 2;
    const uint32_t koff = (((lane >> 4) * 8 + (lane & 7)) * VP + ((lane >> 3) & 1) * 8) * 2;
    const uint32_t voff = ((((lane >> 3) & 1) * 8 + (lane & 7)) * VP + (lane >> 4) * 8) * 2;

    const size_t kvbase = ((size_t)(b * SKL + lr)) * DMODEL + h * HD_ + lh;

    // ---- stage Q through Kh/Kl, extract fragments ----
    {
        const __nv_bfloat16* qh = Qh + ((size_t)(b * SQL + q0 + lr)) * DMODEL + h * HD_ + lh;
        const __nv_bfloat16* ql = Ql + ((size_t)(b * SQL + q0 + lr)) * DMODEL + h * HD_ + lh;
#pragma unroll
        for (int j = 0; j < 4; j++) {
            CP_ASYNC16(aKh + j * 16, qh + j * 8);
            CP_ASYNC16(aKl + j * 16, ql + j * 8);
        }
        CP_COMMIT();
        CP_WAIT0();
        __syncthreads();
    }
    uint32_t qfh[4][4], qfl[4][4];
#pragma unroll
    for (int kc = 0; kc < 4; kc++) {
        LDSM_X4(qfh[kc], bKh + qoff + kc * 32);
        LDSM_X4(qfl[kc], bKl + qoff + kc * 32);
    }
    __syncthreads();   // done reading Kh/Kl (Q staging) before K(0) overwrites

    // ---- prologue: K(0) group, then V(0) group ----
    {
        const __nv_bfloat16* kh = Kgh + kvbase;
        const __nv_bfloat16* kl = Kgl + kvbase;
#pragma unroll
        for (int j = 0; j < 4; j++) {
            CP_ASYNC16(aKh + j * 16, kh + j * 8);
            CP_ASYNC16(aKl + j * 16, kl + j * 8);
        }
        CP_COMMIT();
        const __nv_bfloat16* vh = Vgh + kvbase;
        const __nv_bfloat16* vl = Vgl + kvbase;
#pragma unroll
        for (int j = 0; j < 4; j++) {
            CP_ASYNC16(aVh + j * 16, vh + j * 8);
            CP_ASYNC16(aVl + j * 16, vl + j * 8);
        }
        CP_COMMIT();
    }

    float m0 = -1e30f, m1 = -1e30f, l0 = 0.f, l1 = 0.f;
    float accO[8][4];
#pragma unroll
    for (int dt = 0; dt < 8; dt++)
#pragma unroll
        for (int r = 0; r < 4; r++) accO[dt][r] = 0.f;

    for (int t = 0; t < 8; t++) {
        // ---- K(t) ready (V(t) may still be in flight) ----
        CP_WAIT1();
        __syncthreads();

        // ---- S' = (Q*log2e/8) K^T  (log2 domain) ----
        float accS[8][4];
#pragma unroll
        for (int pr = 0; pr < 4; pr++) {
            uint32_t kh4[4][4], kl4[4][4];
#pragma unroll
            for (int kc = 0; kc < 4; kc++) {
                LDSM_X4(kh4[kc], bKh + koff + pr * (16 * VP * 2) + kc * 32);
                LDSM_X4(kl4[kc], bKl + koff + pr * (16 * VP * 2) + kc * 32);
            }
            int n0 = 2 * pr, n1 = 2 * pr + 1;
            accS[n0][0] = accS[n0][1] = accS[n0][2] = accS[n0][3] = 0.f;
            accS[n1][0] = accS[n1][1] = accS[n1][2] = accS[n1][3] = 0.f;
#pragma unroll
            for (int kc = 0; kc < 4; kc++) {
                mma16816(accS[n0], qfh[kc], &kh4[kc][0]);
                mma16816(accS[n0], qfh[kc], &kl4[kc][0]);
                mma16816(accS[n0], qfl[kc], &kh4[kc][0]);
                mma16816(accS[n1], qfh[kc], &kh4[kc][2]);
                mma16816(accS[n1], qfh[kc], &kl4[kc][2]);
                mma16816(accS[n1], qfl[kc], &kh4[kc][2]);
            }
        }

        // ---- done reading K: prefetch K(t+1) under softmax+PV ----
        __syncthreads();
        if (t + 1 < 8) {
            const size_t off = kvbase + (size_t)(t + 1) * 64 * DMODEL;
            const __nv_bfloat16* kh = Kgh + off;
            const __nv_bfloat16* kl = Kgl + off;
#pragma unroll
            for (int j = 0; j < 4; j++) {
                CP_ASYNC16(aKh + j * 16, kh + j * 8);
                CP_ASYNC16(aKl + j * 16, kl + j * 8);
            }
        }
        CP_COMMIT();

        // ---- online softmax, ex2 domain (single MUFU per value) ----
        float mt0 = -1e30f, mt1 = -1e30f;
#pragma unroll
        for (int nt = 0; nt < 8; nt++) {
            mt0 = fmaxf(mt0, fmaxf(accS[nt][0], accS[nt][1]));
            mt1 = fmaxf(mt1, fmaxf(accS[nt][2], accS[nt][3]));
        }
        mt0 = fmaxf(mt0, __shfl_xor_sync(0xffffffffu, mt0, 1));
        mt0 = fmaxf(mt0, __shfl_xor_sync(0xffffffffu, mt0, 2));
        mt1 = fmaxf(mt1, __shfl_xor_sync(0xffffffffu, mt1, 1));
        mt1 = fmaxf(mt1, __shfl_xor_sync(0xffffffffu, mt1, 2));

        float mn0 = fmaxf(m0, mt0), mn1 = fmaxf(m1, mt1);
        float c0 = ex2f(m0 - mn0), c1 = ex2f(m1 - mn1);
        m0 = mn0; m1 = mn1;

        // exp + sum + pack P per pair (short live ranges help ptxas at 128 regs)
        float s0 = 0.f, s1 = 0.f;
        uint32_t pfh[4][4], pfl[4][4];
#pragma unroll
        for (int kc = 0; kc < 4; kc++) {
#pragma unroll
            for (int half = 0; half < 2; half++) {
                int nt = 2 * kc + half;
                float e0 = ex2f(accS[nt][0] - mn0);
                float e1 = ex2f(accS[nt][1] - mn0);
                float e2 = ex2f(accS[nt][2] - mn1);
                float e3 = ex2f(accS[nt][3] - mn1);
                s0 += e0 + e1;
                s1 += e2 + e3;
                __nv_bfloat16 h0, lo0, h1, lo1;
                split_bf16(e0, h0, lo0);
                split_bf16(e1, h1, lo1);
                pfh[kc][2 * half + 0] = pack_bf2(h0, h1);
                pfl[kc][2 * half + 0] = pack_bf2(lo0, lo1);
                split_bf16(e2, h0, lo0);
                split_bf16(e3, h1, lo1);
                pfh[kc][2 * half + 1] = pack_bf2(h0, h1);
                pfl[kc][2 * half + 1] = pack_bf2(lo0, lo1);
            }
        }
        s0 += __shfl_xor_sync(0xffffffffu, s0, 1);
        s0 += __shfl_xor_sync(0xffffffffu, s0, 2);
        s1 += __shfl_xor_sync(0xffffffffu, s1, 1);
        s1 += __shfl_xor_sync(0xffffffffu, s1, 2);
        l0 = l0 * c0 + s0;
        l1 = l1 * c1 + s1;
#pragma unroll
        for (int dt = 0; dt < 8; dt++) {
            accO[dt][0] *= c0; accO[dt][1] *= c0;
            accO[dt][2] *= c1; accO[dt][3] *= c1;
        }

        // ---- V(t) ready (K(t+1) may still be in flight) ----
        CP_WAIT1();
        __syncthreads();

        // ---- O += P V ----
#pragma unroll
        for (int pr = 0; pr < 4; pr++) {
            uint32_t vh4[4][4], vl4[4][4];
#pragma unroll
            for (int kc = 0; kc < 4; kc++) {
                LDSM_X4_T(vh4[kc], bVh + voff + kc * (16 * VP * 2) + pr * 32);
                LDSM_X4_T(vl4[kc], bVl + voff + kc * (16 * VP * 2) + pr * 32);
            }
            int d0 = 2 * pr, d1 = 2 * pr + 1;
#pragma unroll
            for (int kc = 0; kc < 4; kc++) {
                mma16816(accO[d0], pfh[kc], &vh4[kc][0]);
                mma16816(accO[d0], pfh[kc], &vl4[kc][0]);
                mma16816(accO[d0], pfl[kc], &vh4[kc][0]);
                mma16816(accO[d1], pfh[kc], &vh4[kc][2]);
                mma16816(accO[d1], pfh[kc], &vl4[kc][2]);
                mma16816(accO[d1], pfl[kc], &vh4[kc][2]);
            }
        }

        // ---- done reading V: prefetch V(t+1) under next tile's S ----
        __syncthreads();
        if (t + 1 < 8) {
            const size_t off = kvbase + (size_t)(t + 1) * 64 * DMODEL;
            const __nv_bfloat16* vh = Vgh + off;
            const __nv_bfloat16* vl = Vgl + off;
#pragma unroll
            for (int j = 0; j < 4; j++) {
                CP_ASYNC16(aVh + j * 16, vh + j * 8);
                CP_ASYNC16(aVl + j * 16, vl + j * 8);
            }
        }
        CP_COMMIT();
    }

    float inv0 = 1.f / l0, inv1 = 1.f / l1;
    int row0 = b * SQL + q0 + wid * 16 + fr;
#pragma unroll
    for (int dt = 0; dt < 8; dt++) {
        int col = h * HD_ + dt * 8 + fk;
        float2 o0 = { accO[dt][0] * inv0, accO[dt][1] * inv0 };
        float2 o1 = { accO[dt][2] * inv1, accO[dt][3] * inv1 };
        *(float2*)&Out[(size_t)row0 * DMODEL + col] = o0;
        *(float2*)&Out[(size_t)(row0 + 8) * DMODEL + col] = o1;
    }
}

// ---------------------------------------------------------------------------
extern "C" void kernel_launch(void* const* d_in, const int* in_sizes, int n_in,
                              void* d_out, int out_size)
{
    const float* hidden  = (const float*)d_in[0];
    const float* context = (const float*)d_in[1];
    const float* Wq = (const float*)d_in[2];
    const float* bq = (const float*)d_in[3];
    const float* Wk = (const float*)d_in[4];
    const float* bk = (const float*)d_in[5];
    const float* Wv = (const float*)d_in[6];
    const float* bv = (const float*)d_in[7];
    float* out = (float*)d_out;

    static __nv_bfloat16 *hh = nullptr, *hl = nullptr, *ch = nullptr, *cl = nullptr;
    if (!hh) {
        cudaGetSymbolAddress((void**)&hh, g_Hh);
        cudaGetSymbolAddress((void**)&hl, g_Hl);
        cudaGetSymbolAddress((void**)&ch, g_Ch);
        cudaGetSymbolAddress((void**)&cl, g_Cl);
        cudaFuncSetAttribute(proj_mma, cudaFuncAttributeMaxDynamicSharedMemorySize, PROJ_SMEM);
    }

    const int NEL = B_ * SQL * DMODEL;
    dim3 sgrid(NEL / 4 / 256, 2);
    split_in<<<sgrid, 256>>>(hidden, context, hh, hl, ch, cl);

    dim3 tgrid(DMODEL / 32, DMODEL / 32, 3);
    transpose_w<<<tgrid, dim3(32, 8)>>>(Wq, Wk, Wv);

    dim3 pgrid(DMODEL / 128, (B_ * SQL) / 128, 3);   // (6, 64, 3) = 1152 CTAs
    proj_mma<<<pgrid, 256, PROJ_SMEM>>>(hh, hl, ch, cl, bq, bk, bv);

    dim3 agrid(SQL / 64, NH, B_);                    // (8, 12, 16)
    attn_mma<<<agrid, 128>>>(out);
}